// round 5
// baseline (speedup 1.0000x reference)
#include <cuda_runtime.h>
#include <cstdint>

#define S_SEG 8
#define U_CH 128
#define SU 1024                 // S_SEG * U_CH
#define P_MAX 64
#define GROUPS 4                // z-streams per block (128 threads each)
#define NTHREADS 512
#define TILE_FLOATS (3 * S_SEG * U_CH)   // 3072 floats = 12 KB
#define GRID_BLOCKS 296         // 2 per SM

// Prep outputs (device staging) -> copied to __constant__ each launch.
__device__ uint4 g_meta[P_MAX];           // {off0,off1,off2 (bytes), coeff_bits}
__device__ int   g_pnj[2];                // #j-groups per warp-pair
__device__ int   g_pj[2][S_SEG];          // j value of each group
__device__ int   g_pstart[2][S_SEG + 1];  // global path-range per group

__constant__ uint4 c_meta[P_MAX];
__constant__ int   c_pnj[2];
__constant__ int   c_pj[2][S_SEG];
__constant__ int   c_pstart[2][S_SEG + 1];

__global__ void prep_kernel(const int* __restrict__ path_indices,
                            const float* __restrict__ path_coeff,
                            int P) {
    if (threadIdx.x != 0 || blockIdx.x != 0) return;
    int cnt[S_SEG];
    for (int j = 0; j < S_SEG; j++) cnt[j] = 0;
    for (int p = 0; p < P; p++) cnt[path_indices[p * 4 + 3]]++;

    // Greedy balance: sort j by count desc, assign to lighter pair.
    int ord[S_SEG];
    for (int j = 0; j < S_SEG; j++) ord[j] = j;
    for (int a = 0; a < S_SEG; a++)
        for (int b = a + 1; b < S_SEG; b++)
            if (cnt[ord[b]] > cnt[ord[a]]) { int t = ord[a]; ord[a] = ord[b]; ord[b] = t; }
    int psum[2] = {0, 0};
    int pnj[2] = {0, 0};
    int pj[2][S_SEG];
    for (int a = 0; a < S_SEG; a++) {
        int pair = (psum[1] < psum[0]) ? 1 : 0;
        pj[pair][pnj[pair]++] = ord[a];
        psum[pair] += cnt[ord[a]];
    }

    // Emit meta grouped: pair0's groups then pair1's; record global ranges.
    int pos = 0;
    for (int pair = 0; pair < 2; pair++) {
        g_pnj[pair] = pnj[pair];
        for (int t = 0; t < pnj[pair]; t++) {
            int j = pj[pair][t];
            g_pj[pair][t] = j;
            g_pstart[pair][t] = pos;
            for (int p = 0; p < P; p++) {
                if (path_indices[p * 4 + 3] != j) continue;
                int i0 = path_indices[p * 4 + 0];
                int i1 = path_indices[p * 4 + 1];
                int i2 = path_indices[p * 4 + 2];
                uint4 m;
                m.x = (unsigned)((0 * S_SEG + i0) * U_CH * 4);
                m.y = (unsigned)((1 * S_SEG + i1) * U_CH * 4);
                m.z = (unsigned)((2 * S_SEG + i2) * U_CH * 4);
                m.w = __float_as_uint(path_coeff[p]);
                g_meta[pos++] = m;
            }
            g_pstart[pair][t + 1] = pos;
        }
        for (int t = pnj[pair]; t < S_SEG; t++) {
            g_pj[pair][t] = 0;
            g_pstart[pair][t + 1] = pos;
        }
    }
}

__device__ __forceinline__ unsigned smem_u32(const void* p) {
    unsigned a;
    asm("{ .reg .u64 t; cvta.to.shared.u64 t, %1; cvt.u32.u64 %0, t; }"
        : "=r"(a) : "l"(p));
    return a;
}

__device__ __forceinline__ unsigned long long lds64(unsigned addr) {
    unsigned long long v;
    asm volatile("ld.shared.b64 %0, [%1];" : "=l"(v) : "r"(addr));
    return v;
}

__device__ __forceinline__ unsigned long long mul2(unsigned long long a, unsigned long long b) {
    unsigned long long r;
    asm("mul.rn.f32x2 %0, %1, %2;" : "=l"(r) : "l"(a), "l"(b));
    return r;
}

__device__ __forceinline__ unsigned long long fma2(unsigned long long a, unsigned long long b,
                                                   unsigned long long c) {
    unsigned long long r;
    asm("fma.rn.f32x2 %0, %1, %2, %3;" : "=l"(r) : "l"(a), "l"(b), "l"(c));
    return r;
}

__device__ __forceinline__ unsigned long long add2(unsigned long long a, unsigned long long b) {
    unsigned long long r;
    asm("add.rn.f32x2 %0, %1, %2;" : "=l"(r) : "l"(a), "l"(b));
    return r;
}

__device__ __forceinline__ void cp16(unsigned saddr, const void* gaddr) {
    asm volatile("cp.async.cg.shared.global [%0], [%1], 16;" :: "r"(saddr), "l"(gaddr));
}

__device__ __forceinline__ void cp_commit() {
    asm volatile("cp.async.commit_group;" ::: "memory");
}

template <int N>
__device__ __forceinline__ void cp_wait() {
    asm volatile("cp.async.wait_group %0;" :: "n"(N) : "memory");
}

__device__ __forceinline__ void group_bar(int gid) {
    asm volatile("bar.sync %0, %1;" :: "r"(gid + 1), "r"(128) : "memory");
}

// Stage one z-tile (12 KB) via cp.async: 128 threads x 6 x 16B.
__device__ __forceinline__ void issue_stage(unsigned sdst, long z, int gt,
                                            const float* __restrict__ x0,
                                            const float* __restrict__ x1,
                                            const float* __restrict__ x2) {
    const float* srcs[3] = {x0, x1, x2};
#pragma unroll
    for (int it = 0; it < 6; it++) {
        const int f = it * 128 + gt;          // chunk index (16 B each)
        const int row = f >> 5;
        const int col = f & 31;
        const float* gp = srcs[it >> 1] + z * SU + (row & 7) * U_CH + col * 4;
        cp16(sdst + (unsigned)f * 16, gp);
    }
}

__device__ __forceinline__ void do_path(unsigned long long& acc, unsigned sbase, uint4 m) {
    unsigned long long a = lds64(sbase + m.x);
    unsigned long long b = lds64(sbase + m.y);
    unsigned long long c = lds64(sbase + m.z);
    unsigned long long cc;
    asm("mov.b64 %0, {%1, %1};" : "=l"(cc) : "r"(m.w));
    unsigned long long t = mul2(a, b);
    t = mul2(t, c);
    acc = fma2(t, cc, acc);
}

__global__ __launch_bounds__(NTHREADS, 2)
void ftp4_kernel(const float* __restrict__ x0,
                 const float* __restrict__ x1,
                 const float* __restrict__ x2,
                 float* __restrict__ out,
                 int Z) {
    extern __shared__ float smem[];   // [GROUPS][2][TILE_FLOATS]

    const int tid = threadIdx.x;
    const int ws = tid >> 5;          // warp slot 0..15
    const int g = ws >> 2;            // group / z-stream 0..3
    const int wg = ws & 3;            // warp within group
    const int pair = wg >> 1;         // which j-partition this warp-pair computes
    const int half = wg & 1;          // which 64-channel half
    const int lane = tid & 31;
    const int gt = tid & 127;

    float* buf0 = smem + g * (2 * TILE_FLOATS);
    const unsigned sb0 = smem_u32(buf0);
    const unsigned sb1 = sb0 + TILE_FLOATS * 4;

    const int stream = blockIdx.x * GROUPS + g;
    const int stride = GRID_BLOCKS * GROUPS;            // 1184
    const int nz = (Z > stream) ? ((Z - 1 - stream) / stride + 1) : 0;
    if (nz == 0) return;

    issue_stage(sb0, (long)stream, gt, x0, x1, x2);
    cp_commit();

    const int nj = c_pnj[pair];

    for (int k = 0; k < nz; k++) {
        const long z = (long)stream + (long)k * stride;
        const unsigned scur = (k & 1) ? sb1 : sb0;
        const unsigned snxt = (k & 1) ? sb0 : sb1;

        if (k + 1 < nz) {
            issue_stage(snxt, z + stride, gt, x0, x1, x2);
            cp_commit();
            cp_wait<1>();
        } else {
            cp_wait<0>();
        }
        group_bar(g);   // stage k visible to all 4 warps

        // This warp handles its pair's j-groups over channels [half*64, half*64+64);
        // lane owns 2 channels.
        const unsigned sbase = scur + (unsigned)(half * 256 + lane * 8);
        float* oz = out + z * SU + half * 64 + lane * 2;

        for (int t = 0; t < nj; t++) {
            const int j = c_pj[pair][t];
            const int pb = c_pstart[pair][t];
            const int pe = c_pstart[pair][t + 1];
            unsigned long long acc0 = 0ull, acc1 = 0ull;
            int p = pb;
            for (; p + 1 < pe; p += 2) {
                do_path(acc0, sbase, c_meta[p]);
                do_path(acc1, sbase, c_meta[p + 1]);
            }
            if (p < pe) do_path(acc0, sbase, c_meta[p]);
            unsigned long long acc = add2(acc0, acc1);

            unsigned r0, r1;
            asm("mov.b64 {%0, %1}, %2;" : "=r"(r0), "=r"(r1) : "l"(acc));
            float2 r;
            r.x = __uint_as_float(r0);
            r.y = __uint_as_float(r1);
            *(float2*)(oz + j * U_CH) = r;
        }

        group_bar(g);   // all readers done before buffer reuse
    }
}

extern "C" void kernel_launch(void* const* d_in, const int* in_sizes, int n_in,
                              void* d_out, int out_size) {
    const float* x0 = (const float*)d_in[0];
    const float* x1 = (const float*)d_in[1];
    const float* x2 = (const float*)d_in[2];
    const float* coeff = (const float*)d_in[3];
    const int*   pidx = (const int*)d_in[4];
    float* out = (float*)d_out;

    const int P = in_sizes[3];            // 64
    const int Z = in_sizes[0] / SU;       // 20000

    prep_kernel<<<1, 32>>>(pidx, coeff, P);

    void* a0; void* a1; void* a2; void* a3;
    cudaGetSymbolAddress(&a0, g_meta);
    cudaGetSymbolAddress(&a1, g_pnj);
    cudaGetSymbolAddress(&a2, g_pj);
    cudaGetSymbolAddress(&a3, g_pstart);
    cudaMemcpyToSymbolAsync(c_meta, a0, sizeof(uint4) * P_MAX, 0,
                            cudaMemcpyDeviceToDevice, 0);
    cudaMemcpyToSymbolAsync(c_pnj, a1, sizeof(int) * 2, 0,
                            cudaMemcpyDeviceToDevice, 0);
    cudaMemcpyToSymbolAsync(c_pj, a2, sizeof(int) * 2 * S_SEG, 0,
                            cudaMemcpyDeviceToDevice, 0);
    cudaMemcpyToSymbolAsync(c_pstart, a3, sizeof(int) * 2 * (S_SEG + 1), 0,
                            cudaMemcpyDeviceToDevice, 0);

    const size_t smem_bytes = (size_t)GROUPS * 2 * TILE_FLOATS * sizeof(float); // 96 KB

    static bool attr_set = false;
    if (!attr_set) {
        cudaFuncSetAttribute(ftp4_kernel,
                             cudaFuncAttributeMaxDynamicSharedMemorySize,
                             (int)smem_bytes);
        attr_set = true;
    }

    ftp4_kernel<<<GRID_BLOCKS, NTHREADS, smem_bytes>>>(x0, x1, x2, out, Z);
}

// round 6
// speedup vs baseline: 1.0800x; 1.0800x over previous
#include <cuda_runtime.h>
#include <cstdint>

#define S_SEG 8
#define U_CH 128
#define SU 1024                 // S_SEG * U_CH
#define P_MAX 64
#define GROUPS 4                // z-streams per block (128 threads each)
#define NTHREADS 512
#define TILE_FLOATS (3 * S_SEG * U_CH)   // 3072 floats = 12 KB
#define GRID_BLOCKS 296         // 2 per SM

// All prep outputs in ONE struct -> ONE graph memcpy node per launch.
struct PrepData {
    uint4 meta[P_MAX];           // {off0,off1,off2 (bytes), coeff_bits}, grouped by (pair, j)
    int   pnj[2];                // #j-groups per warp-pair
    int   pjoff[2][S_SEG];       // output byte offset (j * U_CH * 4) per group
    int   pstart[2][S_SEG + 1];  // path-range per group
};

__device__   PrepData g_prep;
__constant__ PrepData c_prep;

__global__ void prep_kernel(const int* __restrict__ path_indices,
                            const float* __restrict__ path_coeff,
                            int P) {
    if (threadIdx.x != 0 || blockIdx.x != 0) return;
    int cnt[S_SEG];
    for (int j = 0; j < S_SEG; j++) cnt[j] = 0;
    for (int p = 0; p < P; p++) cnt[path_indices[p * 4 + 3]]++;

    // Greedy balance: sort j by count desc, assign to lighter pair.
    int ord[S_SEG];
    for (int j = 0; j < S_SEG; j++) ord[j] = j;
    for (int a = 0; a < S_SEG; a++)
        for (int b = a + 1; b < S_SEG; b++)
            if (cnt[ord[b]] > cnt[ord[a]]) { int t = ord[a]; ord[a] = ord[b]; ord[b] = t; }
    int psum[2] = {0, 0};
    int pnj[2] = {0, 0};
    int pj[2][S_SEG];
    for (int a = 0; a < S_SEG; a++) {
        int pair = (psum[1] < psum[0]) ? 1 : 0;
        pj[pair][pnj[pair]++] = ord[a];
        psum[pair] += cnt[ord[a]];
    }

    int pos = 0;
    for (int pair = 0; pair < 2; pair++) {
        g_prep.pnj[pair] = pnj[pair];
        for (int t = 0; t < pnj[pair]; t++) {
            int j = pj[pair][t];
            g_prep.pjoff[pair][t] = j * U_CH * 4;
            g_prep.pstart[pair][t] = pos;
            for (int p = 0; p < P; p++) {
                if (path_indices[p * 4 + 3] != j) continue;
                int i0 = path_indices[p * 4 + 0];
                int i1 = path_indices[p * 4 + 1];
                int i2 = path_indices[p * 4 + 2];
                uint4 m;
                m.x = (unsigned)((0 * S_SEG + i0) * U_CH * 4);
                m.y = (unsigned)((1 * S_SEG + i1) * U_CH * 4);
                m.z = (unsigned)((2 * S_SEG + i2) * U_CH * 4);
                m.w = __float_as_uint(path_coeff[p]);
                g_prep.meta[pos++] = m;
            }
            g_prep.pstart[pair][t + 1] = pos;
        }
        for (int t = pnj[pair]; t < S_SEG; t++) {
            g_prep.pjoff[pair][t] = 0;
            g_prep.pstart[pair][t + 1] = pos;
        }
    }
}

__device__ __forceinline__ unsigned smem_u32(const void* p) {
    unsigned a;
    asm("{ .reg .u64 t; cvta.to.shared.u64 t, %1; cvt.u32.u64 %0, t; }"
        : "=r"(a) : "l"(p));
    return a;
}

__device__ __forceinline__ unsigned long long lds64(unsigned addr) {
    unsigned long long v;
    asm volatile("ld.shared.b64 %0, [%1];" : "=l"(v) : "r"(addr));
    return v;
}

__device__ __forceinline__ unsigned long long mul2(unsigned long long a, unsigned long long b) {
    unsigned long long r;
    asm("mul.rn.f32x2 %0, %1, %2;" : "=l"(r) : "l"(a), "l"(b));
    return r;
}

__device__ __forceinline__ unsigned long long fma2(unsigned long long a, unsigned long long b,
                                                   unsigned long long c) {
    unsigned long long r;
    asm("fma.rn.f32x2 %0, %1, %2, %3;" : "=l"(r) : "l"(a), "l"(b), "l"(c));
    return r;
}

__device__ __forceinline__ unsigned long long add2(unsigned long long a, unsigned long long b) {
    unsigned long long r;
    asm("add.rn.f32x2 %0, %1, %2;" : "=l"(r) : "l"(a), "l"(b));
    return r;
}

__device__ __forceinline__ void cp16(unsigned saddr, const void* gaddr) {
    asm volatile("cp.async.cg.shared.global [%0], [%1], 16;" :: "r"(saddr), "l"(gaddr));
}

__device__ __forceinline__ void cp_commit() {
    asm volatile("cp.async.commit_group;" ::: "memory");
}

template <int N>
__device__ __forceinline__ void cp_wait() {
    asm volatile("cp.async.wait_group %0;" :: "n"(N) : "memory");
}

__device__ __forceinline__ void group_bar(int gid) {
    asm volatile("bar.sync %0, %1;" :: "r"(gid + 1), "r"(128) : "memory");
}

// Stage one z-tile (12 KB) via cp.async: 128 threads x 6 x 16B.
__device__ __forceinline__ void issue_stage(unsigned sdst, long z, int gt,
                                            const float* __restrict__ x0,
                                            const float* __restrict__ x1,
                                            const float* __restrict__ x2) {
    const float* srcs[3] = {x0, x1, x2};
#pragma unroll
    for (int it = 0; it < 6; it++) {
        const int f = it * 128 + gt;          // chunk index (16 B each)
        const int row = f >> 5;
        const int col = f & 31;
        const float* gp = srcs[it >> 1] + z * SU + (row & 7) * U_CH + col * 4;
        cp16(sdst + (unsigned)f * 16, gp);
    }
}

__device__ __forceinline__ void do_path(unsigned long long& acc, unsigned sbase, uint4 m) {
    unsigned long long a = lds64(sbase + m.x);
    unsigned long long b = lds64(sbase + m.y);
    unsigned long long c = lds64(sbase + m.z);
    unsigned long long cc;
    asm("mov.b64 %0, {%1, %1};" : "=l"(cc) : "r"(m.w));
    unsigned long long t = mul2(a, b);
    t = mul2(t, c);
    acc = fma2(t, cc, acc);
}

__global__ __launch_bounds__(NTHREADS, 2)
void ftp4_kernel(const float* __restrict__ x0,
                 const float* __restrict__ x1,
                 const float* __restrict__ x2,
                 float* __restrict__ out,
                 int Z) {
    extern __shared__ float smem[];   // [GROUPS][2][TILE_FLOATS]

    const int tid = threadIdx.x;
    const int ws = tid >> 5;          // warp slot 0..15
    const int g = ws >> 2;            // group / z-stream 0..3
    const int wg = ws & 3;            // warp within group
    const int pair = wg >> 1;         // j-partition for this warp-pair
    const int half = wg & 1;          // 64-channel half
    const int lane = tid & 31;
    const int gt = tid & 127;

    float* buf0 = smem + g * (2 * TILE_FLOATS);
    const unsigned sb0 = smem_u32(buf0);
    const unsigned sb1 = sb0 + TILE_FLOATS * 4;

    const int stream = blockIdx.x * GROUPS + g;
    const int stride = GRID_BLOCKS * GROUPS;            // 1184
    const int nz = (Z > stream) ? ((Z - 1 - stream) / stride + 1) : 0;
    if (nz == 0) return;

    issue_stage(sb0, (long)stream, gt, x0, x1, x2);
    cp_commit();

    const int nj = c_prep.pnj[pair];

    for (int k = 0; k < nz; k++) {
        const long z = (long)stream + (long)k * stride;
        const unsigned scur = (k & 1) ? sb1 : sb0;
        const unsigned snxt = (k & 1) ? sb0 : sb1;

        if (k + 1 < nz) {
            issue_stage(snxt, z + stride, gt, x0, x1, x2);
            cp_commit();
            cp_wait<1>();
        } else {
            cp_wait<0>();
        }
        group_bar(g);   // stage k visible to all 4 warps

        // This warp: its pair's j-groups over channels [half*64, half*64+64);
        // lane owns 2 channels.
        const unsigned sbase = scur + (unsigned)(half * 256 + lane * 8);
        char* ozb = (char*)(out + z * SU + half * 64 + lane * 2);

        for (int t = 0; t < nj; t++) {
            const int joff = c_prep.pjoff[pair][t];
            const int pb = c_prep.pstart[pair][t];
            const int pe = c_prep.pstart[pair][t + 1];
            unsigned long long acc0 = 0ull, acc1 = 0ull;
            int p = pb;
            for (; p + 1 < pe; p += 2) {
                do_path(acc0, sbase, c_prep.meta[p]);
                do_path(acc1, sbase, c_prep.meta[p + 1]);
            }
            if (p < pe) do_path(acc0, sbase, c_prep.meta[p]);
            unsigned long long acc = add2(acc0, acc1);

            unsigned r0, r1;
            asm("mov.b64 {%0, %1}, %2;" : "=r"(r0), "=r"(r1) : "l"(acc));
            float2 r;
            r.x = __uint_as_float(r0);
            r.y = __uint_as_float(r1);
            *(float2*)(ozb + joff) = r;
        }

        group_bar(g);   // all readers done before buffer reuse
    }
}

extern "C" void kernel_launch(void* const* d_in, const int* in_sizes, int n_in,
                              void* d_out, int out_size) {
    const float* x0 = (const float*)d_in[0];
    const float* x1 = (const float*)d_in[1];
    const float* x2 = (const float*)d_in[2];
    const float* coeff = (const float*)d_in[3];
    const int*   pidx = (const int*)d_in[4];
    float* out = (float*)d_out;

    const int P = in_sizes[3];            // 64
    const int Z = in_sizes[0] / SU;       // 20000

    prep_kernel<<<1, 32>>>(pidx, coeff, P);

    void* gaddr = nullptr;
    cudaGetSymbolAddress(&gaddr, g_prep);
    cudaMemcpyToSymbolAsync(c_prep, gaddr, sizeof(PrepData), 0,
                            cudaMemcpyDeviceToDevice, 0);

    const size_t smem_bytes = (size_t)GROUPS * 2 * TILE_FLOATS * sizeof(float); // 96 KB

    static bool attr_set = false;
    if (!attr_set) {
        cudaFuncSetAttribute(ftp4_kernel,
                             cudaFuncAttributeMaxDynamicSharedMemorySize,
                             (int)smem_bytes);
        attr_set = true;
    }

    ftp4_kernel<<<GRID_BLOCKS, NTHREADS, smem_bytes>>>(x0, x1, x2, out, Z);
}

// round 7
// speedup vs baseline: 1.3008x; 1.2044x over previous
#include <cuda_runtime.h>
#include <cstdint>

#define S_SEG 8
#define U_CH 128
#define SU 1024                 // S_SEG * U_CH
#define P_MAX 64
#define GROUPS 4                // z-streams per block (128 threads each)
#define NTHREADS 512
#define TILE_FLOATS (3 * S_SEG * U_CH)   // 3072 floats = 12 KB
#define GRID_BLOCKS 296         // 2 per SM

// All prep outputs in ONE struct -> ONE graph memcpy node per launch.
struct PrepData {
    uint4 meta[P_MAX];           // {off0,off1,off2 (bytes), coeff_bits}, grouped by (pair, j)
    int   pnj[2];                // #j-groups per warp-pair
    int   pjoff[2][S_SEG];       // output byte offset (j * U_CH * 4) per group
    int   pstart[2][S_SEG + 1];  // path-range per group
};

__device__   PrepData g_prep;
__constant__ PrepData c_prep;

__global__ void prep_kernel(const int* __restrict__ path_indices,
                            const float* __restrict__ path_coeff,
                            int P) {
    __shared__ int   sidx[P_MAX * 4];
    __shared__ float scf[P_MAX];
    const int t = threadIdx.x;
    for (int i = t; i < P * 4; i += 32) sidx[i] = path_indices[i];
    for (int i = t; i < P; i += 32) scf[i] = path_coeff[i];
    __syncwarp();
    if (t != 0) return;

    // Count paths per output segment.
    int cnt[S_SEG];
#pragma unroll
    for (int j = 0; j < S_SEG; j++) cnt[j] = 0;
    for (int p = 0; p < P; p++) cnt[sidx[p * 4 + 3]]++;

    // Greedy balance: sort j by count desc, assign to lighter pair.
    int ord[S_SEG];
#pragma unroll
    for (int j = 0; j < S_SEG; j++) ord[j] = j;
#pragma unroll
    for (int a = 0; a < S_SEG; a++)
#pragma unroll
        for (int b = a + 1; b < S_SEG; b++)
            if (cnt[ord[b]] > cnt[ord[a]]) { int tmp = ord[a]; ord[a] = ord[b]; ord[b] = tmp; }
    int psum[2] = {0, 0};
    int pnj[2] = {0, 0};
    int pj[2][S_SEG];
#pragma unroll
    for (int a = 0; a < S_SEG; a++) {
        int pair = (psum[1] < psum[0]) ? 1 : 0;
        pj[pair][pnj[pair]++] = ord[a];
        psum[pair] += cnt[ord[a]];
    }

    // Emission-order bases per j; group descriptors.
    int base[S_SEG];
    int pos = 0;
    for (int pair = 0; pair < 2; pair++) {
        g_prep.pnj[pair] = pnj[pair];
        g_prep.pstart[pair][0] = pos;
        for (int tt = 0; tt < pnj[pair]; tt++) {
            int j = pj[pair][tt];
            g_prep.pjoff[pair][tt] = j * U_CH * 4;
            g_prep.pstart[pair][tt] = pos;
            base[j] = pos;
            pos += cnt[j];
            g_prep.pstart[pair][tt + 1] = pos;
        }
        for (int tt = pnj[pair]; tt < S_SEG; tt++) {
            g_prep.pjoff[pair][tt] = 0;
            g_prep.pstart[pair][tt + 1] = pos;
        }
    }

    // Single placement pass (deterministic order within each j).
    for (int p = 0; p < P; p++) {
        int i0 = sidx[p * 4 + 0];
        int i1 = sidx[p * 4 + 1];
        int i2 = sidx[p * 4 + 2];
        int j  = sidx[p * 4 + 3];
        uint4 m;
        m.x = (unsigned)((0 * S_SEG + i0) * U_CH * 4);
        m.y = (unsigned)((1 * S_SEG + i1) * U_CH * 4);
        m.z = (unsigned)((2 * S_SEG + i2) * U_CH * 4);
        m.w = __float_as_uint(scf[p]);
        g_prep.meta[base[j]++] = m;
    }
}

__device__ __forceinline__ unsigned smem_u32(const void* p) {
    unsigned a;
    asm("{ .reg .u64 t; cvta.to.shared.u64 t, %1; cvt.u32.u64 %0, t; }"
        : "=r"(a) : "l"(p));
    return a;
}

__device__ __forceinline__ unsigned long long lds64(unsigned addr) {
    unsigned long long v;
    asm volatile("ld.shared.b64 %0, [%1];" : "=l"(v) : "r"(addr));
    return v;
}

__device__ __forceinline__ unsigned long long mul2(unsigned long long a, unsigned long long b) {
    unsigned long long r;
    asm("mul.rn.f32x2 %0, %1, %2;" : "=l"(r) : "l"(a), "l"(b));
    return r;
}

__device__ __forceinline__ unsigned long long fma2(unsigned long long a, unsigned long long b,
                                                   unsigned long long c) {
    unsigned long long r;
    asm("fma.rn.f32x2 %0, %1, %2, %3;" : "=l"(r) : "l"(a), "l"(b), "l"(c));
    return r;
}

__device__ __forceinline__ unsigned long long add2(unsigned long long a, unsigned long long b) {
    unsigned long long r;
    asm("add.rn.f32x2 %0, %1, %2;" : "=l"(r) : "l"(a), "l"(b));
    return r;
}

__device__ __forceinline__ void cp16(unsigned saddr, const void* gaddr) {
    asm volatile("cp.async.cg.shared.global [%0], [%1], 16;" :: "r"(saddr), "l"(gaddr));
}

__device__ __forceinline__ void cp_commit() {
    asm volatile("cp.async.commit_group;" ::: "memory");
}

template <int N>
__device__ __forceinline__ void cp_wait() {
    asm volatile("cp.async.wait_group %0;" :: "n"(N) : "memory");
}

__device__ __forceinline__ void group_bar(int gid) {
    asm volatile("bar.sync %0, %1;" :: "r"(gid + 1), "r"(128) : "memory");
}

// Stage one z-tile (12 KB) via cp.async: 128 threads x 6 x 16B.
__device__ __forceinline__ void issue_stage(unsigned sdst, long z, int gt,
                                            const float* __restrict__ x0,
                                            const float* __restrict__ x1,
                                            const float* __restrict__ x2) {
    const float* srcs[3] = {x0, x1, x2};
#pragma unroll
    for (int it = 0; it < 6; it++) {
        const int f = it * 128 + gt;          // chunk index (16 B each)
        const int row = f >> 5;
        const int col = f & 31;
        const float* gp = srcs[it >> 1] + z * SU + (row & 7) * U_CH + col * 4;
        cp16(sdst + (unsigned)f * 16, gp);
    }
}

__device__ __forceinline__ void do_path(unsigned long long& acc, unsigned sbase, uint4 m) {
    unsigned long long a = lds64(sbase + m.x);
    unsigned long long b = lds64(sbase + m.y);
    unsigned long long c = lds64(sbase + m.z);
    unsigned long long cc;
    asm("mov.b64 %0, {%1, %1};" : "=l"(cc) : "r"(m.w));
    unsigned long long t = mul2(a, b);
    t = mul2(t, c);
    acc = fma2(t, cc, acc);
}

__global__ __launch_bounds__(NTHREADS, 2)
void ftp4_kernel(const float* __restrict__ x0,
                 const float* __restrict__ x1,
                 const float* __restrict__ x2,
                 float* __restrict__ out,
                 int Z) {
    extern __shared__ float smem[];   // [GROUPS][2][TILE_FLOATS]

    const int tid = threadIdx.x;
    const int ws = tid >> 5;          // warp slot 0..15
    const int g = ws >> 2;            // group / z-stream 0..3
    const int wg = ws & 3;            // warp within group
    const int pair = wg >> 1;         // j-partition for this warp-pair
    const int half = wg & 1;          // 64-channel half
    const int lane = tid & 31;
    const int gt = tid & 127;

    float* buf0 = smem + g * (2 * TILE_FLOATS);
    const unsigned sb0 = smem_u32(buf0);
    const unsigned sb1 = sb0 + TILE_FLOATS * 4;

    const int stream = blockIdx.x * GROUPS + g;
    const int stride = GRID_BLOCKS * GROUPS;            // 1184
    const int nz = (Z > stream) ? ((Z - 1 - stream) / stride + 1) : 0;
    if (nz == 0) return;

    issue_stage(sb0, (long)stream, gt, x0, x1, x2);
    cp_commit();

    const int nj = c_prep.pnj[pair];

    for (int k = 0; k < nz; k++) {
        const long z = (long)stream + (long)k * stride;
        const unsigned scur = (k & 1) ? sb1 : sb0;
        const unsigned snxt = (k & 1) ? sb0 : sb1;

        if (k + 1 < nz) {
            issue_stage(snxt, z + stride, gt, x0, x1, x2);
            cp_commit();
            cp_wait<1>();
        } else {
            cp_wait<0>();
        }
        group_bar(g);   // stage k visible to all 4 warps

        // This warp: its pair's j-groups over channels [half*64, half*64+64);
        // lane owns 2 channels.
        const unsigned sbase = scur + (unsigned)(half * 256 + lane * 8);
        char* ozb = (char*)(out + z * SU + half * 64 + lane * 2);

        for (int t = 0; t < nj; t++) {
            const int joff = c_prep.pjoff[pair][t];
            const int pb = c_prep.pstart[pair][t];
            const int pe = c_prep.pstart[pair][t + 1];
            unsigned long long acc0 = 0ull, acc1 = 0ull;
            int p = pb;
            for (; p + 1 < pe; p += 2) {
                do_path(acc0, sbase, c_prep.meta[p]);
                do_path(acc1, sbase, c_prep.meta[p + 1]);
            }
            if (p < pe) do_path(acc0, sbase, c_prep.meta[p]);
            unsigned long long acc = add2(acc0, acc1);

            unsigned r0, r1;
            asm("mov.b64 {%0, %1}, %2;" : "=r"(r0), "=r"(r1) : "l"(acc));
            float2 r;
            r.x = __uint_as_float(r0);
            r.y = __uint_as_float(r1);
            *(float2*)(ozb + joff) = r;
        }

        group_bar(g);   // all readers done before buffer reuse
    }
}

extern "C" void kernel_launch(void* const* d_in, const int* in_sizes, int n_in,
                              void* d_out, int out_size) {
    const float* x0 = (const float*)d_in[0];
    const float* x1 = (const float*)d_in[1];
    const float* x2 = (const float*)d_in[2];
    const float* coeff = (const float*)d_in[3];
    const int*   pidx = (const int*)d_in[4];
    float* out = (float*)d_out;

    const int P = in_sizes[3];            // 64
    const int Z = in_sizes[0] / SU;       // 20000

    prep_kernel<<<1, 32>>>(pidx, coeff, P);

    void* gaddr = nullptr;
    cudaGetSymbolAddress(&gaddr, g_prep);
    cudaMemcpyToSymbolAsync(c_prep, gaddr, sizeof(PrepData), 0,
                            cudaMemcpyDeviceToDevice, 0);

    const size_t smem_bytes = (size_t)GROUPS * 2 * TILE_FLOATS * sizeof(float); // 96 KB

    static bool attr_set = false;
    if (!attr_set) {
        cudaFuncSetAttribute(ftp4_kernel,
                             cudaFuncAttributeMaxDynamicSharedMemorySize,
                             (int)smem_bytes);
        attr_set = true;
    }

    ftp4_kernel<<<GRID_BLOCKS, NTHREADS, smem_bytes>>>(x0, x1, x2, out, Z);
}